// round 1
// baseline (speedup 1.0000x reference)
#include <cuda_runtime.h>
#include <cuda_bf16.h>
#include <cstdint>

#define BB 8
#define LL 128
#define DD 768
#define TI 4   // i-rows per block in agg kernel

// scratch: agg[b,i,d]  (8*128*768 floats = 3 MB)
__device__ float g_agg[BB * LL * DD];

// ---------------------------------------------------------------------------
// Kernel 1: agg[b,i,d] = sum_j adj[b,i,j] * (text[b,j,d] + dep[b,j,i,d])
// grid: (B * L/TI) blocks, 256 threads. Each thread owns d0=tid, d0+256, d0+512.
// ---------------------------------------------------------------------------
__global__ void __launch_bounds__(256, 4)
agg_kernel(const float* __restrict__ text,
           const float* __restrict__ adj,
           const float* __restrict__ dep,
           float* __restrict__ agg)
{
    const int b  = blockIdx.x / (LL / TI);
    const int i0 = (blockIdx.x % (LL / TI)) * TI;
    const int tid = threadIdx.x;

    __shared__ float s_adj[TI][LL];
    for (int k = tid; k < TI * LL; k += 256) {
        int ii = k / LL, j = k % LL;
        s_adj[ii][j] = adj[((size_t)b * LL + (i0 + ii)) * LL + j];
    }
    __syncthreads();

    const int d0 = tid;            // 0..255
    float acc[TI][3];
#pragma unroll
    for (int ii = 0; ii < TI; ++ii) {
        acc[ii][0] = 0.f; acc[ii][1] = 0.f; acc[ii][2] = 0.f;
    }

    const float* textb = text + (size_t)b * LL * DD;
    const float* depb  = dep  + (size_t)b * LL * LL * DD;

#pragma unroll 2
    for (int j = 0; j < LL; ++j) {
        const float t0 = textb[(size_t)j * DD + d0];
        const float t1 = textb[(size_t)j * DD + d0 + 256];
        const float t2 = textb[(size_t)j * DD + d0 + 512];
        const float* dj = depb + (size_t)j * LL * DD + (size_t)i0 * DD + d0;
#pragma unroll
        for (int ii = 0; ii < TI; ++ii) {
            const float a = s_adj[ii][j];
            const float e0 = dj[ii * DD];
            const float e1 = dj[ii * DD + 256];
            const float e2 = dj[ii * DD + 512];
            acc[ii][0] = fmaf(a, t0 + e0, acc[ii][0]);
            acc[ii][1] = fmaf(a, t1 + e1, acc[ii][1]);
            acc[ii][2] = fmaf(a, t2 + e2, acc[ii][2]);
        }
    }

#pragma unroll
    for (int ii = 0; ii < TI; ++ii) {
        float* o = agg + ((size_t)b * LL + (i0 + ii)) * DD + d0;
        o[0]   = acc[ii][0];
        o[256] = acc[ii][1];
        o[512] = acc[ii][2];
    }
}

// ---------------------------------------------------------------------------
// Kernel 2: out[m, n] = relu( sum_k agg[m, k] * W[k, n] + bias[n] )
// M = B*L = 1024, N = 768, K = 768.
// 64x64 block tile, BK=16, 256 threads (16x16), 4x4 microtile per thread.
// ---------------------------------------------------------------------------
#define BM 64
#define BN 64
#define BK 16

__global__ void __launch_bounds__(256, 2)
gemm_bias_relu(const float* __restrict__ A,   // [M, K]
               const float* __restrict__ W,   // [K, N]
               const float* __restrict__ bias,
               float* __restrict__ out)       // [M, N]
{
    const int M = BB * LL;   // 1024
    const int N = DD;        // 768
    const int K = DD;        // 768

    const int n0 = blockIdx.x * BN;
    const int m0 = blockIdx.y * BM;
    const int tid = threadIdx.x;
    const int tx = tid % 16;          // n-direction
    const int ty = tid / 16;          // m-direction

    __shared__ float As[BK][BM];      // transposed A tile: As[k][m]
    __shared__ float Ws[BK][BN];

    float acc[4][4];
#pragma unroll
    for (int i = 0; i < 4; ++i)
#pragma unroll
        for (int j = 0; j < 4; ++j) acc[i][j] = 0.f;

    // A tile load mapping: each thread loads one float4 (row = tid/4, col4 = tid%4)
    const int a_row = tid >> 2;       // 0..63
    const int a_c4  = (tid & 3) * 4;  // 0,4,8,12
    // W tile load mapping: each thread loads one float4 (row = tid/16, col4 = tid%16)
    const int w_row = tid >> 4;       // 0..15
    const int w_c4  = (tid & 15) * 4; // 0..60

    for (int k0 = 0; k0 < K; k0 += BK) {
        // load A tile (64 x 16) -> transposed into As[k][m]
        float4 av = *reinterpret_cast<const float4*>(
            &A[(size_t)(m0 + a_row) * K + k0 + a_c4]);
        As[a_c4 + 0][a_row] = av.x;
        As[a_c4 + 1][a_row] = av.y;
        As[a_c4 + 2][a_row] = av.z;
        As[a_c4 + 3][a_row] = av.w;

        // load W tile (16 x 64)
        *reinterpret_cast<float4*>(&Ws[w_row][w_c4]) =
            *reinterpret_cast<const float4*>(&W[(size_t)(k0 + w_row) * N + n0 + w_c4]);

        __syncthreads();

#pragma unroll
        for (int k = 0; k < BK; ++k) {
            float4 a4 = *reinterpret_cast<const float4*>(&As[k][ty * 4]);
            float4 w4 = *reinterpret_cast<const float4*>(&Ws[k][tx * 4]);
            float am[4] = {a4.x, a4.y, a4.z, a4.w};
            float wn[4] = {w4.x, w4.y, w4.z, w4.w};
#pragma unroll
            for (int i = 0; i < 4; ++i)
#pragma unroll
                for (int j = 0; j < 4; ++j)
                    acc[i][j] = fmaf(am[i], wn[j], acc[i][j]);
        }
        __syncthreads();
    }

    // epilogue: bias + relu
    const float4 bv = *reinterpret_cast<const float4*>(&bias[n0 + tx * 4]);
    const float bn[4] = {bv.x, bv.y, bv.z, bv.w};
#pragma unroll
    for (int i = 0; i < 4; ++i) {
        float4 r;
        r.x = fmaxf(acc[i][0] + bn[0], 0.f);
        r.y = fmaxf(acc[i][1] + bn[1], 0.f);
        r.z = fmaxf(acc[i][2] + bn[2], 0.f);
        r.w = fmaxf(acc[i][3] + bn[3], 0.f);
        *reinterpret_cast<float4*>(
            &out[(size_t)(m0 + ty * 4 + i) * N + n0 + tx * 4]) = r;
    }
}

// ---------------------------------------------------------------------------
extern "C" void kernel_launch(void* const* d_in, const int* in_sizes, int n_in,
                              void* d_out, int out_size)
{
    const float* text = (const float*)d_in[0];
    const float* adj  = (const float*)d_in[1];
    const float* dep  = (const float*)d_in[2];
    const float* W    = (const float*)d_in[3];
    const float* bias = (const float*)d_in[4];
    float* out = (float*)d_out;

    float* agg;
    cudaGetSymbolAddress((void**)&agg, g_agg);

    agg_kernel<<<BB * (LL / TI), 256>>>(text, adj, dep, agg);

    dim3 grid(DD / BN, (BB * LL) / BM);   // (12, 16)
    gemm_bias_relu<<<grid, 256>>>(agg, W, bias, out);
}

// round 3
// speedup vs baseline: 1.3568x; 1.3568x over previous
#include <cuda_runtime.h>
#include <cuda_bf16.h>
#include <cstdint>

#define BB 8
#define LL 128
#define DD 768
#define TI 4

#define GM (BB * LL)   // 1024
#define GN DD          // 768
#define GK DD          // 768

// ---------------- global scratch (no allocation allowed) ----------------
__device__ __nv_bfloat16 g_Ahi[GM * GK];
__device__ __nv_bfloat16 g_Alo[GM * GK];
__device__ __nv_bfloat16 g_Whi[GN * GK];   // [n][k]  (W transposed)
__device__ __nv_bfloat16 g_Wlo[GN * GK];

// ---------------------------------------------------------------------------
// Kernel 1: agg[b,i,:] = sum_j adj[b,i,j] * (text[b,j,:] + dep[b,j,i,:])
// outputs bf16 hi/lo split of agg directly.
// ---------------------------------------------------------------------------
__global__ void __launch_bounds__(256, 4)
agg_kernel(const float* __restrict__ text,
           const float* __restrict__ adj,
           const float* __restrict__ dep,
           __nv_bfloat16* __restrict__ Ahi,
           __nv_bfloat16* __restrict__ Alo)
{
    const int b  = blockIdx.x / (LL / TI);
    const int i0 = (blockIdx.x % (LL / TI)) * TI;
    const int tid = threadIdx.x;

    __shared__ float s_adj[TI][LL];
    for (int k = tid; k < TI * LL; k += 256) {
        int ii = k / LL, j = k % LL;
        s_adj[ii][j] = adj[((size_t)b * LL + (i0 + ii)) * LL + j];
    }
    __syncthreads();

    const int d0 = tid;
    float acc[TI][3];
#pragma unroll
    for (int ii = 0; ii < TI; ++ii) { acc[ii][0] = 0.f; acc[ii][1] = 0.f; acc[ii][2] = 0.f; }

    const float* textb = text + (size_t)b * LL * DD;
    const float* depb  = dep  + (size_t)b * LL * LL * DD;

#pragma unroll 2
    for (int j = 0; j < LL; ++j) {
        const float t0 = textb[(size_t)j * DD + d0];
        const float t1 = textb[(size_t)j * DD + d0 + 256];
        const float t2 = textb[(size_t)j * DD + d0 + 512];
        const float* dj = depb + (size_t)j * LL * DD + (size_t)i0 * DD + d0;
#pragma unroll
        for (int ii = 0; ii < TI; ++ii) {
            const float a = s_adj[ii][j];
            const float e0 = dj[ii * DD];
            const float e1 = dj[ii * DD + 256];
            const float e2 = dj[ii * DD + 512];
            acc[ii][0] = fmaf(a, t0 + e0, acc[ii][0]);
            acc[ii][1] = fmaf(a, t1 + e1, acc[ii][1]);
            acc[ii][2] = fmaf(a, t2 + e2, acc[ii][2]);
        }
    }

#pragma unroll
    for (int ii = 0; ii < TI; ++ii) {
#pragma unroll
        for (int p = 0; p < 3; ++p) {
            float v = acc[ii][p];
            __nv_bfloat16 h = __float2bfloat16(v);
            __nv_bfloat16 l = __float2bfloat16(v - __bfloat162float(h));
            size_t idx = ((size_t)b * LL + (i0 + ii)) * (size_t)GK + d0 + 256 * p;
            Ahi[idx] = h;
            Alo[idx] = l;
        }
    }
}

// ---------------------------------------------------------------------------
// Kernel 2: transpose + split W[k][n] fp32 -> Wt_hi/lo[n][k] bf16
// ---------------------------------------------------------------------------
__global__ void __launch_bounds__(256)
wsplit_kernel(const float* __restrict__ W,
              __nv_bfloat16* __restrict__ Whi,
              __nv_bfloat16* __restrict__ Wlo)
{
    __shared__ float t[32][33];
    const int n0 = blockIdx.x * 32;
    const int k0 = blockIdx.y * 32;
    const int tx = threadIdx.x & 31;
    const int ty = threadIdx.x >> 5;   // 0..7

#pragma unroll
    for (int i = 0; i < 4; ++i)
        t[ty + 8 * i][tx] = W[(size_t)(k0 + ty + 8 * i) * GN + n0 + tx];
    __syncthreads();

#pragma unroll
    for (int i = 0; i < 4; ++i) {
        const int n = n0 + ty + 8 * i;
        const int k = k0 + tx;
        float v = t[tx][ty + 8 * i];
        __nv_bfloat16 h = __float2bfloat16(v);
        __nv_bfloat16 l = __float2bfloat16(v - __bfloat162float(h));
        Whi[(size_t)n * GK + k] = h;
        Wlo[(size_t)n * GK + k] = l;
    }
}

// ---------------------------------------------------------------------------
// Kernel 3: HMMA bf16 GEMM (mma.sync m16n8k16), hi/lo 3-pass, fp32 accum.
// out[m][n] = relu(sum_k A[m][k]*W[k][n] + bias[n]);   B = W^T rows [n][k].
// 64x64 CTA tile, BK=64 double-buffered via cp.async, 4 warps (32x32 each).
// ---------------------------------------------------------------------------
#define BM 64
#define BN 64
#define BK 64
#define NCH (GK / BK)          // 12
#define PITCH 144              // 128B data + 16B pad; conflict-free ldmatrix
#define TILE_B (BM * PITCH)    // 9216 bytes
#define STAGE_B (4 * TILE_B)   // Ahi, Alo, Bhi, Blo
#define GEMM_SMEM (2 * STAGE_B)

__device__ __forceinline__ uint32_t smem_u32(const void* p) {
    uint32_t a;
    asm("{ .reg .u64 t; cvta.to.shared.u64 t, %1; cvt.u32.u64 %0, t; }" : "=r"(a) : "l"(p));
    return a;
}

__device__ __forceinline__ void cp_async16(uint32_t dst, const void* src) {
    asm volatile("cp.async.cg.shared.global [%0], [%1], 16;" :: "r"(dst), "l"(src));
}
#define CP_COMMIT() asm volatile("cp.async.commit_group;")
#define CP_WAIT1()  asm volatile("cp.async.wait_group 1;")

__device__ __forceinline__ void ldsm_x4(uint32_t* r, uint32_t addr) {
    asm volatile("ldmatrix.sync.aligned.m8n8.x4.shared.b16 {%0,%1,%2,%3}, [%4];"
                 : "=r"(r[0]), "=r"(r[1]), "=r"(r[2]), "=r"(r[3]) : "r"(addr));
}
__device__ __forceinline__ void ldsm_x2(uint32_t* r, uint32_t addr) {
    asm volatile("ldmatrix.sync.aligned.m8n8.x2.shared.b16 {%0,%1}, [%2];"
                 : "=r"(r[0]), "=r"(r[1]) : "r"(addr));
}
__device__ __forceinline__ void mma_bf16(float* c, const uint32_t* a, const uint32_t* b) {
    asm volatile(
        "mma.sync.aligned.m16n8k16.row.col.f32.bf16.bf16.f32 "
        "{%0,%1,%2,%3}, {%4,%5,%6,%7}, {%8,%9}, {%0,%1,%2,%3};"
        : "+f"(c[0]), "+f"(c[1]), "+f"(c[2]), "+f"(c[3])
        : "r"(a[0]), "r"(a[1]), "r"(a[2]), "r"(a[3]), "r"(b[0]), "r"(b[1]));
}

__global__ void __launch_bounds__(128, 2)
gemm_hmma(const __nv_bfloat16* __restrict__ Ahi,
          const __nv_bfloat16* __restrict__ Alo,
          const __nv_bfloat16* __restrict__ Whi,
          const __nv_bfloat16* __restrict__ Wlo,
          const float* __restrict__ bias,
          float* __restrict__ out)
{
    extern __shared__ char smem[];
    const uint32_t sbase = smem_u32(smem);
    const int tid = threadIdx.x;
    const int wid = tid >> 5;
    const int lid = tid & 31;

    const int n0 = blockIdx.x * BN;
    const int m0 = blockIdx.y * BM;

    const int warp_m = wid >> 1;     // 0..1
    const int warp_n = wid & 1;      // 0..1

    // load mapping: idx = tid + 128*i, i in 0..3 per tile; row=idx/8, c16=idx%8
    const int l_row = tid >> 3;      // 0..15 base row (stride 16 over i)
    const int l_c16 = tid & 7;

    float acc[2][4][4];
#pragma unroll
    for (int mt = 0; mt < 2; ++mt)
#pragma unroll
        for (int nt = 0; nt < 4; ++nt)
#pragma unroll
            for (int r = 0; r < 4; ++r) acc[mt][nt][r] = 0.f;

    // ---- issue loads for a chunk into stage s ----
    auto load_chunk = [&](int c, int s) {
        const int k0 = c * BK;
        const uint32_t stage = sbase + s * STAGE_B;
#pragma unroll
        for (int i = 0; i < 4; ++i) {
            const int row = l_row + 16 * i;
            const uint32_t doff = (uint32_t)(row * PITCH + l_c16 * 16);
            const size_t ga = (size_t)(m0 + row) * GK + k0 + l_c16 * 8;
            const size_t gb = (size_t)(n0 + row) * GK + k0 + l_c16 * 8;
            cp_async16(stage + 0 * TILE_B + doff, Ahi + ga);
            cp_async16(stage + 1 * TILE_B + doff, Alo + ga);
            cp_async16(stage + 2 * TILE_B + doff, Whi + gb);
            cp_async16(stage + 3 * TILE_B + doff, Wlo + gb);
        }
    };

    load_chunk(0, 0); CP_COMMIT();
    load_chunk(1, 1); CP_COMMIT();

    // ldmatrix lane address components
    const int a_sub = lid >> 3;                   // 0..3
    const int a_row_off = (a_sub & 1) * 8 + (lid & 7);
    const int a_col_off = (a_sub >> 1) * 16;      // 0 or 16 bytes
    const int b_sub = (lid >> 3) & 1;             // 0..1
    const int b_row_off = lid & 7;
    const int b_col_off = b_sub * 16;

    for (int c = 0; c < NCH; ++c) {
        CP_WAIT1();
        __syncthreads();

        const uint32_t stage = sbase + (c & 1) * STAGE_B;
        const uint32_t tAhi = stage + 0 * TILE_B;
        const uint32_t tAlo = stage + 1 * TILE_B;
        const uint32_t tBhi = stage + 2 * TILE_B;
        const uint32_t tBlo = stage + 3 * TILE_B;

#pragma unroll
        for (int ks = 0; ks < BK / 16; ++ks) {
            const int kb = ks * 32;               // byte offset of k-step
            uint32_t ah[2][4], al[2][4], bh[4][2], bl[4][2];
#pragma unroll
            for (int mt = 0; mt < 2; ++mt) {
                const uint32_t ao =
                    (uint32_t)((warp_m * 32 + mt * 16 + a_row_off) * PITCH + kb + a_col_off);
                ldsm_x4(ah[mt], tAhi + ao);
                ldsm_x4(al[mt], tAlo + ao);
            }
#pragma unroll
            for (int nt = 0; nt < 4; ++nt) {
                const uint32_t bo =
                    (uint32_t)((warp_n * 32 + nt * 8 + b_row_off) * PITCH + kb + b_col_off);
                ldsm_x2(bh[nt], tBhi + bo);
                ldsm_x2(bl[nt], tBlo + bo);
            }
#pragma unroll
            for (int mt = 0; mt < 2; ++mt)
#pragma unroll
                for (int nt = 0; nt < 4; ++nt) {
                    mma_bf16(acc[mt][nt], ah[mt], bh[nt]);
                    mma_bf16(acc[mt][nt], ah[mt], bl[nt]);
                    mma_bf16(acc[mt][nt], al[mt], bh[nt]);
                }
        }
        __syncthreads();

        if (c + 2 < NCH) load_chunk(c + 2, c & 1);
        CP_COMMIT();
    }

    // ---- epilogue: bias + relu, direct stores ----
    const int col_base = n0 + warp_n * 32 + 2 * (lid & 3);
    const int row_base = m0 + warp_m * 32 + (lid >> 2);
#pragma unroll
    for (int mt = 0; mt < 2; ++mt) {
#pragma unroll
        for (int nt = 0; nt < 4; ++nt) {
            const int col = col_base + nt * 8;
            const float2 bv = *reinterpret_cast<const float2*>(&bias[col]);
#pragma unroll
            for (int h = 0; h < 2; ++h) {
                const int row = row_base + mt * 16 + h * 8;
                float2 o;
                o.x = fmaxf(acc[mt][nt][2 * h + 0] + bv.x, 0.f);
                o.y = fmaxf(acc[mt][nt][2 * h + 1] + bv.y, 0.f);
                *reinterpret_cast<float2*>(&out[(size_t)row * GN + col]) = o;
            }
        }
    }
}

// ---------------------------------------------------------------------------
extern "C" void kernel_launch(void* const* d_in, const int* in_sizes, int n_in,
                              void* d_out, int out_size)
{
    const float* text = (const float*)d_in[0];
    const float* adj  = (const float*)d_in[1];
    const float* dep  = (const float*)d_in[2];
    const float* W    = (const float*)d_in[3];
    const float* bias = (const float*)d_in[4];
    float* out = (float*)d_out;

    __nv_bfloat16 *Ahi, *Alo, *Whi, *Wlo;
    cudaGetSymbolAddress((void**)&Ahi, g_Ahi);
    cudaGetSymbolAddress((void**)&Alo, g_Alo);
    cudaGetSymbolAddress((void**)&Whi, g_Whi);
    cudaGetSymbolAddress((void**)&Wlo, g_Wlo);

    cudaFuncSetAttribute(gemm_hmma, cudaFuncAttributeMaxDynamicSharedMemorySize, GEMM_SMEM);

    wsplit_kernel<<<dim3(GN / 32, GK / 32), 256>>>(W, Whi, Wlo);
    agg_kernel<<<BB * (LL / TI), 256>>>(text, adj, dep, Ahi, Alo);
    gemm_hmma<<<dim3(GN / BN, GM / BM), 128, GEMM_SMEM>>>(Ahi, Alo, Whi, Wlo, bias, out);
}